// round 2
// baseline (speedup 1.0000x reference)
#include <cuda_runtime.h>
#include <cuda_bf16.h>
#include <cstdint>

// Problem constants
#define MDIM 8192
#define KDIM 4096
#define NDIM 4096

// Scratch (no cudaMalloc allowed)
__device__ int8_t g_xq[(size_t)MDIM * KDIM];        // 32 MB quantized activations
__device__ float  g_ascale[MDIM];
__device__ int8_t g_wt[(size_t)NDIM * KDIM];        // 16 MB transposed weights [N, K]
__device__ int    g_w_is_i32;                       // 1 if weight buffer holds int32
__device__ int    g_sb_swap;                        // 1 if (cand2, cand3) = (bias, scale)

// ---------------------------------------------------------------------------
// Kernel 0: deterministic input-format detection (single thread).
// ---------------------------------------------------------------------------
__global__ void detect_kernel(const int* __restrict__ w,
                              const float* __restrict__ c2,
                              const float* __restrict__ c3) {
    if (threadIdx.x != 0) return;
    // (a) weight dtype: int32 values all lie in [-128,127]; random int8 byte
    //     quadruplets essentially never do for 2048 consecutive words.
    int in_range = 1;
    for (int i = 0; i < 2048; i++) {
        int v = w[i];
        if (v < -128 || v > 127) { in_range = 0; break; }
    }
    g_w_is_i32 = in_range;
    // (b) weight_scale is all-positive in (1e-4, 0.0101); bias is mixed-sign.
    int c2_scale_like = 1;
    for (int i = 0; i < 256; i++) {
        float v = c2[i];
        if (!(v > 0.0f && v < 0.02f)) { c2_scale_like = 0; break; }
    }
    g_sb_swap = c2_scale_like ? 0 : 1;
}

// ---------------------------------------------------------------------------
// Kernel 1: per-row dynamic quantization of x. One block per row.
// ---------------------------------------------------------------------------
__global__ void quantize_rows_kernel(const float* __restrict__ x) {
    const int row = blockIdx.x;
    const int tid = threadIdx.x;

    const float4* xr = reinterpret_cast<const float4*>(x) + (size_t)row * (KDIM / 4);
    float4 v[4];
    float amax = 0.0f;
#pragma unroll
    for (int i = 0; i < 4; i++) {
        v[i] = xr[tid + i * 256];
        amax = fmaxf(amax, fmaxf(fmaxf(fabsf(v[i].x), fabsf(v[i].y)),
                                 fmaxf(fabsf(v[i].z), fabsf(v[i].w))));
    }
#pragma unroll
    for (int o = 16; o; o >>= 1)
        amax = fmaxf(amax, __shfl_xor_sync(0xFFFFFFFFu, amax, o));

    __shared__ float sm[8];
    __shared__ float s_scale;
    if ((tid & 31) == 0) sm[tid >> 5] = amax;
    __syncthreads();
    if (tid == 0) {
        float m = sm[0];
#pragma unroll
        for (int i = 1; i < 8; i++) m = fmaxf(m, sm[i]);
        float s = fmaxf(m / 127.0f, 1e-8f);
        g_ascale[row] = s;
        s_scale = s;
    }
    __syncthreads();

    const float inv = 1.0f / s_scale;
    unsigned int* oq = reinterpret_cast<unsigned int*>(g_xq) + (size_t)row * (KDIM / 4);
#pragma unroll
    for (int i = 0; i < 4; i++) {
        int q0 = max(-128, min(127, __float2int_rn(v[i].x * inv)));
        int q1 = max(-128, min(127, __float2int_rn(v[i].y * inv)));
        int q2 = max(-128, min(127, __float2int_rn(v[i].z * inv)));
        int q3 = max(-128, min(127, __float2int_rn(v[i].w * inv)));
        unsigned int packed = (q0 & 0xFF) | ((q1 & 0xFF) << 8) |
                              ((q2 & 0xFF) << 16) | ((q3 & 0xFF) << 24);
        oq[tid + i * 256] = packed;
    }
}

// ---------------------------------------------------------------------------
// Kernel 2: transpose weight_q [K, N] -> g_wt [N, K]; handles int8 OR int32
// source encoding (uniform branch on g_w_is_i32).
// ---------------------------------------------------------------------------
__global__ void transpose_w_kernel(const void* __restrict__ wraw) {
    __shared__ uint8_t t[128][36];  // [n][k], padded
    const int tid = threadIdx.x;
    const int n0 = blockIdx.x * 128;
    const int k0 = blockIdx.y * 32;

    if (g_w_is_i32) {
        const int* w = (const int*)wraw;
#pragma unroll
        for (int it = 0; it < 4; it++) {
            int i = tid + it * 256;
            int k = i >> 5;            // 0..31
            int n4 = i & 31;           // word of 4 n
            int4 wv = *reinterpret_cast<const int4*>(
                w + (size_t)(k0 + k) * NDIM + n0 + n4 * 4);
            t[n4 * 4 + 0][k] = (uint8_t)wv.x;
            t[n4 * 4 + 1][k] = (uint8_t)wv.y;
            t[n4 * 4 + 2][k] = (uint8_t)wv.z;
            t[n4 * 4 + 3][k] = (uint8_t)wv.w;
        }
    } else {
        const int8_t* w = (const int8_t*)wraw;
#pragma unroll
        for (int it = 0; it < 4; it++) {
            int i = tid + it * 256;
            int k = i >> 5;
            int n4 = i & 31;
            unsigned int wv = *reinterpret_cast<const unsigned int*>(
                w + (size_t)(k0 + k) * NDIM + n0 + n4 * 4);
            t[n4 * 4 + 0][k] = (uint8_t)(wv & 0xFF);
            t[n4 * 4 + 1][k] = (uint8_t)((wv >> 8) & 0xFF);
            t[n4 * 4 + 2][k] = (uint8_t)((wv >> 16) & 0xFF);
            t[n4 * 4 + 3][k] = (uint8_t)((wv >> 24) & 0xFF);
        }
    }
    __syncthreads();

#pragma unroll
    for (int it = 0; it < 4; it++) {
        int i = tid + it * 256;
        int n = i >> 3;                // 0..127
        int kw = i & 7;                // 0..7
        unsigned int wv = (unsigned int)t[n][kw * 4 + 0] |
                          ((unsigned int)t[n][kw * 4 + 1] << 8) |
                          ((unsigned int)t[n][kw * 4 + 2] << 16) |
                          ((unsigned int)t[n][kw * 4 + 3] << 24);
        *reinterpret_cast<unsigned int*>(g_wt + (size_t)(n0 + n) * KDIM + k0 + kw * 4) = wv;
    }
}

// ---------------------------------------------------------------------------
// Kernel 3: int8 GEMM (mma.m16n8k32) + fused dequant epilogue.
// Block tile 128x128, K-chunk 64, double-buffered cp.async.
// ---------------------------------------------------------------------------
__device__ __forceinline__ void cp_async16(uint32_t smem, const void* g) {
    asm volatile("cp.async.cg.shared.global [%0], [%1], 16;\n" ::"r"(smem), "l"(g));
}

#define SROW 80
#define STAGE_BYTES (128 * SROW)

__global__ __launch_bounds__(256, 2) void gemm_s8_kernel(
    const float* __restrict__ cand2, const float* __restrict__ cand3,
    float* __restrict__ out) {
    __shared__ __align__(16) uint8_t sA[2][STAGE_BYTES];
    __shared__ __align__(16) uint8_t sB[2][STAGE_BYTES];

    const int tid = threadIdx.x;
    const int bm = blockIdx.y * 128;
    const int bn = blockIdx.x * 128;
    const int wid = tid >> 5, lane = tid & 31;
    const int wm = (wid >> 2) * 64;
    const int wn = (wid & 3) * 32;
    const int g = lane >> 2, tig = lane & 3;

    int acc[4][4][4];
#pragma unroll
    for (int a = 0; a < 4; a++)
#pragma unroll
        for (int b = 0; b < 4; b++)
#pragma unroll
            for (int c = 0; c < 4; c++) acc[a][b][c] = 0;

    const uint32_t sAb = (uint32_t)__cvta_generic_to_shared(sA);
    const uint32_t sBb = (uint32_t)__cvta_generic_to_shared(sB);

    const int r_ld = tid >> 2;
    const int kc_ld = (tid & 3) * 16;
    const int8_t* gA0 = g_xq + (size_t)(bm + r_ld) * KDIM + kc_ld;
    const int8_t* gB0 = g_wt + (size_t)(bn + r_ld) * KDIM + kc_ld;

#define LOAD_STAGE(s, kt)                                                        \
    do {                                                                         \
        int k0_ = (kt)*64;                                                       \
        cp_async16(sAb + (s)*STAGE_BYTES + r_ld * SROW + kc_ld, gA0 + k0_);      \
        cp_async16(sAb + (s)*STAGE_BYTES + (r_ld + 64) * SROW + kc_ld,           \
                   gA0 + (size_t)64 * KDIM + k0_);                               \
        cp_async16(sBb + (s)*STAGE_BYTES + r_ld * SROW + kc_ld, gB0 + k0_);      \
        cp_async16(sBb + (s)*STAGE_BYTES + (r_ld + 64) * SROW + kc_ld,           \
                   gB0 + (size_t)64 * KDIM + k0_);                               \
    } while (0)

    LOAD_STAGE(0, 0);
    asm volatile("cp.async.commit_group;\n" ::);

    const int KT = KDIM / 64;
    for (int kt = 0; kt < KT; kt++) {
        if (kt + 1 < KT) LOAD_STAGE((kt + 1) & 1, kt + 1);
        asm volatile("cp.async.commit_group;\n" ::);
        asm volatile("cp.async.wait_group 1;\n" ::);
        __syncthreads();

        const int s = kt & 1;
#pragma unroll
        for (int ks = 0; ks < 2; ks++) {
            const int kb = ks * 32;
            uint32_t af[4][4];
#pragma unroll
            for (int mf = 0; mf < 4; mf++) {
                const int r0 = (wm + mf * 16 + g) * SROW + kb + tig * 4;
                af[mf][0] = *reinterpret_cast<const uint32_t*>(&sA[s][r0]);
                af[mf][1] = *reinterpret_cast<const uint32_t*>(&sA[s][r0 + 8 * SROW]);
                af[mf][2] = *reinterpret_cast<const uint32_t*>(&sA[s][r0 + 16]);
                af[mf][3] = *reinterpret_cast<const uint32_t*>(&sA[s][r0 + 8 * SROW + 16]);
            }
            uint32_t bf[4][2];
#pragma unroll
            for (int nf = 0; nf < 4; nf++) {
                const int r0 = (wn + nf * 8 + g) * SROW + kb + tig * 4;
                bf[nf][0] = *reinterpret_cast<const uint32_t*>(&sB[s][r0]);
                bf[nf][1] = *reinterpret_cast<const uint32_t*>(&sB[s][r0 + 16]);
            }
#pragma unroll
            for (int mf = 0; mf < 4; mf++) {
#pragma unroll
                for (int nf = 0; nf < 4; nf++) {
                    asm volatile(
                        "mma.sync.aligned.m16n8k32.row.col.s32.s8.s8.s32 "
                        "{%0,%1,%2,%3}, {%4,%5,%6,%7}, {%8,%9}, {%0,%1,%2,%3};\n"
                        : "+r"(acc[mf][nf][0]), "+r"(acc[mf][nf][1]),
                          "+r"(acc[mf][nf][2]), "+r"(acc[mf][nf][3])
                        : "r"(af[mf][0]), "r"(af[mf][1]), "r"(af[mf][2]),
                          "r"(af[mf][3]), "r"(bf[nf][0]), "r"(bf[nf][1]));
                }
            }
        }
        __syncthreads();
    }

    // Epilogue: resolve scale/bias pointers by detection flag, dequant + bias.
    const float* wscale = g_sb_swap ? cand3 : cand2;
    const float* bias   = g_sb_swap ? cand2 : cand3;
#pragma unroll
    for (int mf = 0; mf < 4; mf++) {
        const int r0 = bm + wm + mf * 16 + g;
        const int r1 = r0 + 8;
        const float as0 = g_ascale[r0];
        const float as1 = g_ascale[r1];
#pragma unroll
        for (int nf = 0; nf < 4; nf++) {
            const int c0 = bn + wn + nf * 8 + 2 * tig;
            const float ws0 = wscale[c0], ws1 = wscale[c0 + 1];
            const float bv0 = bias[c0], bv1 = bias[c0 + 1];
            float2 o0 = make_float2((float)acc[mf][nf][0] * as0 * ws0 + bv0,
                                    (float)acc[mf][nf][1] * as0 * ws1 + bv1);
            float2 o1 = make_float2((float)acc[mf][nf][2] * as1 * ws0 + bv0,
                                    (float)acc[mf][nf][3] * as1 * ws1 + bv1);
            *reinterpret_cast<float2*>(&out[(size_t)r0 * NDIM + c0]) = o0;
            *reinterpret_cast<float2*>(&out[(size_t)r1 * NDIM + c0]) = o1;
        }
    }
}

// ---------------------------------------------------------------------------
extern "C" void kernel_launch(void* const* d_in, const int* in_sizes, int n_in,
                              void* d_out, int out_size) {
    // Resolve inputs by element count (robust to metadata ordering).
    int idx_x = -1, idx_w = -1, idx_a = -1, idx_b = -1;
    for (int i = 0; i < n_in; i++) {
        long s = in_sizes[i];
        if (s == (long)MDIM * KDIM) idx_x = i;
        else if (s == (long)KDIM * NDIM) idx_w = i;
        else if (idx_a < 0) idx_a = i;
        else idx_b = i;
    }
    if (idx_x < 0 || idx_w < 0 || idx_a < 0 || idx_b < 0) {
        idx_x = 0; idx_w = 1; idx_a = 2; idx_b = 3;
    }

    const float* x   = (const float*)d_in[idx_x];
    const void*  wq  = d_in[idx_w];
    const float* c2  = (const float*)d_in[idx_a];
    const float* c3  = (const float*)d_in[idx_b];
    float* out = (float*)d_out;

    detect_kernel<<<1, 32>>>((const int*)wq, c2, c3);
    quantize_rows_kernel<<<MDIM, 256>>>(x);
    transpose_w_kernel<<<dim3(NDIM / 128, KDIM / 32), 256>>>(wq);
    gemm_s8_kernel<<<dim3(NDIM / 128, MDIM / 128), 256>>>(c2, c3, out);
}